// round 12
// baseline (speedup 1.0000x reference)
#include <cuda_runtime.h>
#include <cuda_fp16.h>
#include <math.h>
#include <stdint.h>

#define F 128
#define MAXN 50048
#define MAXE 800064

// Scratch (__device__ globals; no allocation allowed)
__device__ __align__(16) float g_W[F * F];              // evolved weight
__device__ __align__(16) float g_xw[(size_t)MAXN * F];  // x @ W (fp32, self term)
__device__ __align__(16) __half g_xwh[(size_t)MAXN * F];// x @ W (fp16, gathers)
__device__ float g_dinv[MAXN];                          // deg -> rsqrt(deg)
__device__ int   g_cnt[MAXN];                           // per-dst edge count
__device__ int   g_off[MAXN];                           // exclusive scan
__device__ int   g_cur[MAXN];                           // placement cursors
__device__ unsigned g_scanstate[256];                   // lookback status
__device__ __align__(16) int2 g_edge[MAXE];             // dst-sorted (src, coef)

__device__ __forceinline__ uint32_t f2tf32(float f) {
    uint32_t u;
    asm("cvt.rna.tf32.f32 %0, %1;" : "=r"(u) : "f"(f));
    return u;
}

// ---------------------------------------------------------------------------
// 1) GRU weight evolution fused with counter/state init.
// ---------------------------------------------------------------------------
__global__ void k_gru_zero(const float* __restrict__ W0,
                           const float* __restrict__ Wih,
                           const float* __restrict__ Whh,
                           const float* __restrict__ bih,
                           const float* __restrict__ bhh, int N) {
    int t = blockIdx.x * blockDim.x + threadIdx.x;
    if (t < N) { g_cnt[t] = 0; g_dinv[t] = 1.0f; }   // self-loop weight = 1
    if (t < 256) g_scanstate[t] = 0;                  // reset lookback state
    if (t >= F * F) return;
    int i = t >> 7;
    int j = t & 127;

    const float* w0r = W0 + i * F;
    const float* a_r = Wih + (size_t)j * F;
    const float* a_z = Wih + (size_t)(j + F) * F;
    const float* a_n = Wih + (size_t)(j + 2 * F) * F;
    const float* h_r = Whh + (size_t)j * F;
    const float* h_z = Whh + (size_t)(j + F) * F;
    const float* h_n = Whh + (size_t)(j + 2 * F) * F;

    float ir = 0.f, iz = 0.f, in_ = 0.f, hr = 0.f, hz = 0.f, hn = 0.f;
#pragma unroll 8
    for (int k = 0; k < F; k++) {
        float w0 = __ldg(w0r + k);
        ir += w0 * __ldg(a_r + k);
        iz += w0 * __ldg(a_z + k);
        in_ += w0 * __ldg(a_n + k);
        hr += w0 * __ldg(h_r + k);
        hz += w0 * __ldg(h_z + k);
        hn += w0 * __ldg(h_n + k);
    }
    ir += __ldg(bih + j);
    iz += __ldg(bih + j + F);
    in_ += __ldg(bih + j + 2 * F);
    hr += __ldg(bhh + j);
    hz += __ldg(bhh + j + F);
    hn += __ldg(bhh + j + 2 * F);

    float r = 1.f / (1.f + expf(-(ir + hr)));
    float z = 1.f / (1.f + expf(-(iz + hz)));
    float n = tanhf(in_ + r * hn);
    g_W[t] = (1.f - z) * n + z * __ldg(W0 + t);
}

// ---------------------------------------------------------------------------
// 2) histogram (2 edges/thread): per-dst count + weighted degree
// ---------------------------------------------------------------------------
__global__ void k_hist(const int* __restrict__ dst,
                       const float* __restrict__ ew, int E) {
    int t = blockIdx.x * blockDim.x + threadIdx.x;
    int e0 = t * 2;
    if (e0 + 1 < E) {
        int2 dd = __ldg(reinterpret_cast<const int2*>(dst) + t);
        float2 ww = __ldg(reinterpret_cast<const float2*>(ew) + t);
        atomicAdd(&g_cnt[dd.x], 1);
        atomicAdd(&g_dinv[dd.x], ww.x);
        atomicAdd(&g_cnt[dd.y], 1);
        atomicAdd(&g_dinv[dd.y], ww.y);
    } else if (e0 < E) {
        int d = __ldg(dst + e0);
        atomicAdd(&g_cnt[d], 1);
        atomicAdd(&g_dinv[d], __ldg(ew + e0));
    }
}

// ---------------------------------------------------------------------------
// 3) Single-pass scan (decoupled lookback) + dinv finalize + cursor init.
// ---------------------------------------------------------------------------
__global__ void k_scan(int N) {
    __shared__ int sh[256];
    __shared__ int s_prev;
    int tid = threadIdx.x;
    int gid = blockIdx.x * 256 + tid;

    if (gid < N) {  // dinv finalize (hist complete)
        float d = g_dinv[gid];
        g_dinv[gid] = (d > 0.f) ? rsqrtf(d) : 0.f;
    }
    int v = (gid < N) ? g_cnt[gid] : 0;
    sh[tid] = v;
    __syncthreads();
#pragma unroll
    for (int o = 1; o < 256; o <<= 1) {
        int t = (tid >= o) ? sh[tid - o] : 0;
        __syncthreads();
        sh[tid] += t;
        __syncthreads();
    }
    int total = sh[255];

    if (tid == 0) {
        int prev = 0;
        if (blockIdx.x == 0) {
            atomicExch(&g_scanstate[0], (2u << 30) | (unsigned)total);
        } else {
            atomicExch(&g_scanstate[blockIdx.x], (1u << 30) | (unsigned)total);
            int b = blockIdx.x - 1;
            while (true) {
                unsigned s = atomicAdd(&g_scanstate[b], 0u);
                unsigned st = s >> 30;
                if (st == 0u) continue;                 // not published yet
                prev += (int)(s & 0x3FFFFFFFu);
                if (st == 2u) break;                    // full prefix known
                b--;
            }
            atomicExch(&g_scanstate[blockIdx.x],
                       (2u << 30) | (unsigned)(prev + total));
        }
        s_prev = prev;
    }
    __syncthreads();
    if (gid < N) {
        int off = s_prev + sh[tid] - v;   // exclusive
        g_off[gid] = off;
        g_cur[gid] = off;
    }
}

// ---------------------------------------------------------------------------
// 4) FUSED placement + tensor-core GEMM.
//    GEMM warp tile reduced to 16x64 (acc = 32 regs) and launch_bounds(256,4)
//    so the fused kernel fits 4 blocks/SM — placement occupancy doubled vs R11.
//    GEMM block: 128 rows x 64 cols; gemm block id gb -> row0=(gb>>1)*128,
//    col0=(gb&1)*64.
// ---------------------------------------------------------------------------
__global__ void __launch_bounds__(256, 4) k_place_gemm(
        const int* __restrict__ src, const int* __restrict__ dst,
        const float* __restrict__ ew, int E,
        const float* __restrict__ x, int N, int gemmBlocks) {

    if ((int)blockIdx.x >= gemmBlocks) {
        // ---------------- placement: 2 edges/thread ----------------
        int t = (blockIdx.x - gemmBlocks) * blockDim.x + threadIdx.x;
        int e0 = t * 2;
        if (e0 + 1 < E) {
            int2 ss = __ldg(reinterpret_cast<const int2*>(src) + t);
            int2 dd = __ldg(reinterpret_cast<const int2*>(dst) + t);
            float2 ww = __ldg(reinterpret_cast<const float2*>(ew) + t);
            float c0 = g_dinv[ss.x] * ww.x * g_dinv[dd.x];
            float c1 = g_dinv[ss.y] * ww.y * g_dinv[dd.y];
            int p0 = atomicAdd(&g_cur[dd.x], 1);
            g_edge[p0] = make_int2(ss.x, __float_as_int(c0));
            int p1 = atomicAdd(&g_cur[dd.y], 1);
            g_edge[p1] = make_int2(ss.y, __float_as_int(c1));
        } else if (e0 < E) {
            int s = __ldg(src + e0);
            int d = __ldg(dst + e0);
            float c = g_dinv[s] * __ldg(ew + e0) * g_dinv[d];
            int p = atomicAdd(&g_cur[d], 1);
            g_edge[p] = make_int2(s, __float_as_int(c));
        }
        return;
    }

    // ---------------- GEMM: g_xw = x @ g_W (tf32 mma, fp32 accum) ---------
    __shared__ float Xs[128 * 36];    // 18.4 KB
    __shared__ float Ws[32 * 72];     //  9.2 KB (64 cols + 8 pad)
    int tid = threadIdx.x;
    int warp = tid >> 5, lane = tid & 31;
    int gb = blockIdx.x;
    int row0 = (gb >> 1) * 128;
    int col0 = (gb & 1) * 64;
    int gid = lane >> 2;
    int tig = lane & 3;

    float acc[8][4];
#pragma unroll
    for (int nt = 0; nt < 8; nt++)
#pragma unroll
        for (int c = 0; c < 4; c++) acc[nt][c] = 0.f;

    for (int kt = 0; kt < 4; kt++) {
        __syncthreads();
        // x tile: 128 rows x 32 k (tf32-rounded)
#pragma unroll
        for (int i = 0; i < 4; i++) {
            int e = tid + i * 256;           // 0..1023 float4s
            int r = e >> 3, kg = e & 7;
            float4 v = make_float4(0.f, 0.f, 0.f, 0.f);
            if (row0 + r < N)
                v = __ldg(reinterpret_cast<const float4*>(x + (size_t)(row0 + r) * F + kt * 32) + kg);
            v.x = __uint_as_float(f2tf32(v.x));
            v.y = __uint_as_float(f2tf32(v.y));
            v.z = __uint_as_float(f2tf32(v.z));
            v.w = __uint_as_float(f2tf32(v.w));
            reinterpret_cast<float4*>(Xs)[r * 9 + kg] = v;
        }
        // W chunk: 32 k-rows x 64 cols (this block's half)
#pragma unroll
        for (int i = 0; i < 2; i++) {
            int e = tid + i * 256;           // 0..511 float4s
            int r = e >> 4, cg = e & 15;
            float4 v = reinterpret_cast<const float4*>(g_W + (size_t)(kt * 32 + r) * F + col0)[cg];
            v.x = __uint_as_float(f2tf32(v.x));
            v.y = __uint_as_float(f2tf32(v.y));
            v.z = __uint_as_float(f2tf32(v.z));
            v.w = __uint_as_float(f2tf32(v.w));
            reinterpret_cast<float4*>(Ws)[r * 18 + cg] = v;  // 72 floats = 18 float4
        }
        __syncthreads();

#pragma unroll
        for (int ks = 0; ks < 4; ks++) {
            int k0 = ks * 8;
            int ar = warp * 16 + gid;
            uint32_t a0 = __float_as_uint(Xs[ar * 36 + k0 + tig]);
            uint32_t a1 = __float_as_uint(Xs[(ar + 8) * 36 + k0 + tig]);
            uint32_t a2 = __float_as_uint(Xs[ar * 36 + k0 + tig + 4]);
            uint32_t a3 = __float_as_uint(Xs[(ar + 8) * 36 + k0 + tig + 4]);
#pragma unroll
            for (int nt = 0; nt < 8; nt++) {
                int col = nt * 8 + gid;
                uint32_t b0 = __float_as_uint(Ws[(k0 + tig) * 72 + col]);
                uint32_t b1 = __float_as_uint(Ws[(k0 + tig + 4) * 72 + col]);
                asm volatile(
                    "mma.sync.aligned.m16n8k8.row.col.f32.tf32.tf32.f32 "
                    "{%0,%1,%2,%3}, {%4,%5,%6,%7}, {%8,%9}, {%0,%1,%2,%3};"
                    : "+f"(acc[nt][0]), "+f"(acc[nt][1]), "+f"(acc[nt][2]), "+f"(acc[nt][3])
                    : "r"(a0), "r"(a1), "r"(a2), "r"(a3), "r"(b0), "r"(b1));
            }
        }
    }

    int r_lo = row0 + warp * 16 + gid;
    int r_hi = r_lo + 8;
#pragma unroll
    for (int nt = 0; nt < 8; nt++) {
        int c = col0 + nt * 8 + 2 * tig;
        if (r_lo < N) {
            *reinterpret_cast<float2*>(g_xw + (size_t)r_lo * F + c) =
                make_float2(acc[nt][0], acc[nt][1]);
            *reinterpret_cast<__half2*>(g_xwh + (size_t)r_lo * F + c) =
                __float22half2_rn(make_float2(acc[nt][0], acc[nt][1]));
        }
        if (r_hi < N) {
            *reinterpret_cast<float2*>(g_xw + (size_t)r_hi * F + c) =
                make_float2(acc[nt][2], acc[nt][3]);
            *reinterpret_cast<__half2*>(g_xwh + (size_t)r_hi * F + c) =
                __float22half2_rn(make_float2(acc[nt][2], acc[nt][3]));
        }
    }
}

// ---------------------------------------------------------------------------
// 5) Fused aggregation + tanh + linear output. Warp per dst node.
//    fp16 gathers (half the L2 traffic of fp32; 8x less quantization error
//    than the failed bf16 attempt). Self-loop term stays fp32. 8-deep MLP.
// ---------------------------------------------------------------------------
__global__ void k_agg_out(const float* __restrict__ wlin,
                          const float* __restrict__ blin,
                          float* __restrict__ out, int N) {
    int node = (blockIdx.x * blockDim.x + threadIdx.x) >> 5;
    int lane = threadIdx.x & 31;
    if (node >= N) return;

    float di = g_dinv[node];
    float4 v0 = reinterpret_cast<const float4*>(g_xw + (size_t)node * F)[lane];
    float sc = di * di;
    float ax = sc * v0.x, ay = sc * v0.y, az = sc * v0.z, aw = sc * v0.w;

    int e = g_off[node];
    int end = e + g_cnt[node];

    for (; e + 8 <= end; e += 8) {
        int2 q[8];
        uint2 a[8];
#pragma unroll
        for (int i = 0; i < 8; i++) q[i] = __ldg(g_edge + e + i);
#pragma unroll
        for (int i = 0; i < 8; i++)
            a[i] = __ldg(reinterpret_cast<const uint2*>(g_xwh + (size_t)q[i].x * F) + lane);
#pragma unroll
        for (int i = 0; i < 8; i++) {
            float c = __int_as_float(q[i].y);
            float2 lo = __half22float2(*reinterpret_cast<__half2*>(&a[i].x));
            float2 hi = __half22float2(*reinterpret_cast<__half2*>(&a[i].y));
            ax += c * lo.x; ay += c * lo.y; az += c * hi.x; aw += c * hi.y;
        }
    }
    for (; e + 2 <= end; e += 2) {
        int2 q0 = __ldg(g_edge + e);
        int2 q1 = __ldg(g_edge + e + 1);
        uint2 a0 = __ldg(reinterpret_cast<const uint2*>(g_xwh + (size_t)q0.x * F) + lane);
        uint2 a1 = __ldg(reinterpret_cast<const uint2*>(g_xwh + (size_t)q1.x * F) + lane);
        float c0 = __int_as_float(q0.y), c1 = __int_as_float(q1.y);
        float2 lo0 = __half22float2(*reinterpret_cast<__half2*>(&a0.x));
        float2 hi0 = __half22float2(*reinterpret_cast<__half2*>(&a0.y));
        float2 lo1 = __half22float2(*reinterpret_cast<__half2*>(&a1.x));
        float2 hi1 = __half22float2(*reinterpret_cast<__half2*>(&a1.y));
        ax += c0 * lo0.x + c1 * lo1.x;
        ay += c0 * lo0.y + c1 * lo1.y;
        az += c0 * hi0.x + c1 * hi1.x;
        aw += c0 * hi0.y + c1 * hi1.y;
    }
    if (e < end) {
        int2 q = __ldg(g_edge + e);
        uint2 a = __ldg(reinterpret_cast<const uint2*>(g_xwh + (size_t)q.x * F) + lane);
        float c = __int_as_float(q.y);
        float2 lo = __half22float2(*reinterpret_cast<__half2*>(&a.x));
        float2 hi = __half22float2(*reinterpret_cast<__half2*>(&a.y));
        ax += c * lo.x; ay += c * lo.y; az += c * hi.x; aw += c * hi.y;
    }

    float4 wv = reinterpret_cast<const float4*>(wlin)[lane];
    float sum = tanhf(ax) * wv.x + tanhf(ay) * wv.y +
                tanhf(az) * wv.z + tanhf(aw) * wv.w;
#pragma unroll
    for (int o = 16; o; o >>= 1) sum += __shfl_xor_sync(0xffffffffu, sum, o);
    if (lane == 0) out[node] = sum + __ldg(blin);
}

// ---------------------------------------------------------------------------
extern "C" void kernel_launch(void* const* d_in, const int* in_sizes, int n_in,
                              void* d_out, int out_size) {
    const float* x    = (const float*)d_in[0];
    const int*   ei   = (const int*)d_in[1];
    const float* ew   = (const float*)d_in[2];
    const float* W0   = (const float*)d_in[3];
    const float* Wih  = (const float*)d_in[4];
    const float* Whh  = (const float*)d_in[5];
    const float* bih  = (const float*)d_in[6];
    const float* bhh  = (const float*)d_in[7];
    const float* wlin = (const float*)d_in[8];
    const float* blin = (const float*)d_in[9];
    float* out = (float*)d_out;

    int N = in_sizes[0] / F;
    int E = in_sizes[2];
    const int* src = ei;
    const int* dst = ei + E;
    int nb = (N + 255) / 256;                       // 196 for N=50000 (<=256)
    int gemmBlocks = ((N + 127) / 128) * 2;         // 2 col-halves per row tile
    int placeBlocks = (E + 511) / 512;              // 2 edges/thread

    k_gru_zero<<<nb, 256>>>(W0, Wih, Whh, bih, bhh, N);
    k_hist<<<(E + 511) / 512, 256>>>(dst, ew, E);
    k_scan<<<nb, 256>>>(N);
    k_place_gemm<<<gemmBlocks + placeBlocks, 256>>>(src, dst, ew, E, x, N, gemmBlocks);
    k_agg_out<<<(N + 7) / 8, 256>>>(wlin, blin, out, N);
}

// round 14
// speedup vs baseline: 1.0480x; 1.0480x over previous
#include <cuda_runtime.h>
#include <cuda_fp16.h>
#include <math.h>
#include <stdint.h>

#define F 128
#define MAXN 50048
#define MAXE 800064

// Scratch (__device__ globals; no allocation allowed).
// INVARIANT at kernel_launch entry (zero-init at load, restored every round):
//   g_cnt == 0, g_deg == 0, g_scanstate == 0.
__device__ __align__(16) float g_W[F * F];              // evolved weight
__device__ __align__(16) float g_xw[(size_t)MAXN * F];  // x @ W (fp32, self term)
__device__ __align__(16) __half g_xwh[(size_t)MAXN * F];// x @ W (fp16, gathers)
__device__ float g_dinv[MAXN];                          // rsqrt(deg)
__device__ float g_deg[MAXN];                           // weighted degree accum (zero-invariant)
__device__ int   g_cnt[MAXN];                           // per-dst edge count (zero-invariant)
__device__ int   g_off[MAXN];                           // exclusive scan
__device__ int   g_cur[MAXN];                           // placement cursors (end = off+cnt after place)
__device__ unsigned g_scanstate[256];                   // lookback status (zero-invariant)
__device__ __align__(16) int2 g_edge[MAXE];             // dst-sorted (src, coef)

__device__ __forceinline__ uint32_t f2tf32(float f) {
    uint32_t u;
    asm("cvt.rna.tf32.f32 %0, %1;" : "=r"(u) : "f"(f));
    return u;
}

// ---------------------------------------------------------------------------
// 1) FUSED: GRU weight evolution (blocks [0,gruBlocks)) + edge histogram
//    (remaining blocks). Independent work — hist relies on the zero-invariant
//    of g_cnt/g_deg instead of an init kernel.
// ---------------------------------------------------------------------------
__global__ void k_gru_hist(const float* __restrict__ W0,
                           const float* __restrict__ Wih,
                           const float* __restrict__ Whh,
                           const float* __restrict__ bih,
                           const float* __restrict__ bhh,
                           const int* __restrict__ dst,
                           const float* __restrict__ ew, int E, int gruBlocks) {
    if ((int)blockIdx.x >= gruBlocks) {
        // ---------------- histogram: 2 edges/thread ----------------
        int t = (blockIdx.x - gruBlocks) * blockDim.x + threadIdx.x;
        int e0 = t * 2;
        if (e0 + 1 < E) {
            int2 dd = __ldg(reinterpret_cast<const int2*>(dst) + t);
            float2 ww = __ldg(reinterpret_cast<const float2*>(ew) + t);
            atomicAdd(&g_cnt[dd.x], 1);
            atomicAdd(&g_deg[dd.x], ww.x);
            atomicAdd(&g_cnt[dd.y], 1);
            atomicAdd(&g_deg[dd.y], ww.y);
        } else if (e0 < E) {
            int d = __ldg(dst + e0);
            atomicAdd(&g_cnt[d], 1);
            atomicAdd(&g_deg[d], __ldg(ew + e0));
        }
        return;
    }

    int t = blockIdx.x * blockDim.x + threadIdx.x;
    if (t >= F * F) return;
    int i = t >> 7;
    int j = t & 127;

    const float* w0r = W0 + i * F;
    const float* a_r = Wih + (size_t)j * F;
    const float* a_z = Wih + (size_t)(j + F) * F;
    const float* a_n = Wih + (size_t)(j + 2 * F) * F;
    const float* h_r = Whh + (size_t)j * F;
    const float* h_z = Whh + (size_t)(j + F) * F;
    const float* h_n = Whh + (size_t)(j + 2 * F) * F;

    float ir = 0.f, iz = 0.f, in_ = 0.f, hr = 0.f, hz = 0.f, hn = 0.f;
#pragma unroll 8
    for (int k = 0; k < F; k++) {
        float w0 = __ldg(w0r + k);
        ir += w0 * __ldg(a_r + k);
        iz += w0 * __ldg(a_z + k);
        in_ += w0 * __ldg(a_n + k);
        hr += w0 * __ldg(h_r + k);
        hz += w0 * __ldg(h_z + k);
        hn += w0 * __ldg(h_n + k);
    }
    ir += __ldg(bih + j);
    iz += __ldg(bih + j + F);
    in_ += __ldg(bih + j + 2 * F);
    hr += __ldg(bhh + j);
    hz += __ldg(bhh + j + F);
    hn += __ldg(bhh + j + 2 * F);

    float r = 1.f / (1.f + expf(-(ir + hr)));
    float z = 1.f / (1.f + expf(-(iz + hz)));
    float n = tanhf(in_ + r * hn);
    g_W[t] = (1.f - z) * n + z * __ldg(W0 + t);
}

// ---------------------------------------------------------------------------
// 2) Single-pass scan (decoupled lookback) + dinv finalize + cursor init.
//    Restores the zero-invariant of g_cnt / g_deg after consuming them.
// ---------------------------------------------------------------------------
__global__ void k_scan(int N) {
    __shared__ int sh[256];
    __shared__ int s_prev;
    int tid = threadIdx.x;
    int gid = blockIdx.x * 256 + tid;

    int v = 0;
    if (gid < N) {
        float d = g_deg[gid];
        g_deg[gid] = 0.f;                       // restore invariant
        g_dinv[gid] = rsqrtf(d + 1.0f);         // +1 = self-loop weight; deg>=1
        v = g_cnt[gid];
        g_cnt[gid] = 0;                         // restore invariant
    }
    sh[tid] = v;
    __syncthreads();
#pragma unroll
    for (int o = 1; o < 256; o <<= 1) {
        int t = (tid >= o) ? sh[tid - o] : 0;
        __syncthreads();
        sh[tid] += t;
        __syncthreads();
    }
    int total = sh[255];

    if (tid == 0) {
        int prev = 0;
        if (blockIdx.x == 0) {
            atomicExch(&g_scanstate[0], (2u << 30) | (unsigned)total);
        } else {
            atomicExch(&g_scanstate[blockIdx.x], (1u << 30) | (unsigned)total);
            int b = blockIdx.x - 1;
            while (true) {
                unsigned s = atomicAdd(&g_scanstate[b], 0u);
                unsigned st = s >> 30;
                if (st == 0u) continue;                 // not published yet
                prev += (int)(s & 0x3FFFFFFFu);
                if (st == 2u) break;                    // full prefix known
                b--;
            }
            atomicExch(&g_scanstate[blockIdx.x],
                       (2u << 30) | (unsigned)(prev + total));
        }
        s_prev = prev;
    }
    __syncthreads();
    if (gid < N) {
        int off = s_prev + sh[tid] - v;   // exclusive
        g_off[gid] = off;
        g_cur[gid] = off;
    }
}

// ---------------------------------------------------------------------------
// 3) FUSED placement + tensor-core GEMM (R11's measured-best 16x128 tile).
//    First placement block also restores g_scanstate invariant.
// ---------------------------------------------------------------------------
__global__ void __launch_bounds__(256) k_place_gemm(
        const int* __restrict__ src, const int* __restrict__ dst,
        const float* __restrict__ ew, int E,
        const float* __restrict__ x, int N, int gemmBlocks) {

    if ((int)blockIdx.x >= gemmBlocks) {
        // ---------------- placement: 2 edges/thread ----------------
        if ((int)blockIdx.x == gemmBlocks)
            g_scanstate[threadIdx.x] = 0;       // restore invariant (scan done)
        int t = (blockIdx.x - gemmBlocks) * blockDim.x + threadIdx.x;
        int e0 = t * 2;
        if (e0 + 1 < E) {
            int2 ss = __ldg(reinterpret_cast<const int2*>(src) + t);
            int2 dd = __ldg(reinterpret_cast<const int2*>(dst) + t);
            float2 ww = __ldg(reinterpret_cast<const float2*>(ew) + t);
            float c0 = g_dinv[ss.x] * ww.x * g_dinv[dd.x];
            float c1 = g_dinv[ss.y] * ww.y * g_dinv[dd.y];
            int p0 = atomicAdd(&g_cur[dd.x], 1);
            g_edge[p0] = make_int2(ss.x, __float_as_int(c0));
            int p1 = atomicAdd(&g_cur[dd.y], 1);
            g_edge[p1] = make_int2(ss.y, __float_as_int(c1));
        } else if (e0 < E) {
            int s = __ldg(src + e0);
            int d = __ldg(dst + e0);
            float c = g_dinv[s] * __ldg(ew + e0) * g_dinv[d];
            int p = atomicAdd(&g_cur[d], 1);
            g_edge[p] = make_int2(s, __float_as_int(c));
        }
        return;
    }

    // ---------------- GEMM: g_xw = x @ g_W (tf32 mma, fp32 accum) ---------
    __shared__ float Xs[128 * 36];
    __shared__ float Ws[32 * 136];
    int tid = threadIdx.x;
    int warp = tid >> 5, lane = tid & 31;
    int row0 = blockIdx.x * 128;
    int gid = lane >> 2;
    int tig = lane & 3;

    float acc[16][4];
#pragma unroll
    for (int nt = 0; nt < 16; nt++)
#pragma unroll
        for (int c = 0; c < 4; c++) acc[nt][c] = 0.f;

    for (int kt = 0; kt < 4; kt++) {
        __syncthreads();
#pragma unroll
        for (int i = 0; i < 4; i++) {
            int e = tid + i * 256;
            int r = e >> 3, kg = e & 7;
            float4 v = make_float4(0.f, 0.f, 0.f, 0.f);
            if (row0 + r < N)
                v = __ldg(reinterpret_cast<const float4*>(x + (size_t)(row0 + r) * F + kt * 32) + kg);
            v.x = __uint_as_float(f2tf32(v.x));
            v.y = __uint_as_float(f2tf32(v.y));
            v.z = __uint_as_float(f2tf32(v.z));
            v.w = __uint_as_float(f2tf32(v.w));
            reinterpret_cast<float4*>(Xs)[r * 9 + kg] = v;
        }
#pragma unroll
        for (int i = 0; i < 4; i++) {
            int e = tid + i * 256;
            int r = e >> 5, cg = e & 31;
            float4 v = reinterpret_cast<const float4*>(g_W + (size_t)(kt * 32 + r) * F)[cg];
            v.x = __uint_as_float(f2tf32(v.x));
            v.y = __uint_as_float(f2tf32(v.y));
            v.z = __uint_as_float(f2tf32(v.z));
            v.w = __uint_as_float(f2tf32(v.w));
            reinterpret_cast<float4*>(Ws)[r * 34 + cg] = v;
        }
        __syncthreads();

#pragma unroll
        for (int ks = 0; ks < 4; ks++) {
            int k0 = ks * 8;
            int ar = warp * 16 + gid;
            uint32_t a0 = __float_as_uint(Xs[ar * 36 + k0 + tig]);
            uint32_t a1 = __float_as_uint(Xs[(ar + 8) * 36 + k0 + tig]);
            uint32_t a2 = __float_as_uint(Xs[ar * 36 + k0 + tig + 4]);
            uint32_t a3 = __float_as_uint(Xs[(ar + 8) * 36 + k0 + tig + 4]);
#pragma unroll
            for (int nt = 0; nt < 16; nt++) {
                int col = nt * 8 + gid;
                uint32_t b0 = __float_as_uint(Ws[(k0 + tig) * 136 + col]);
                uint32_t b1 = __float_as_uint(Ws[(k0 + tig + 4) * 136 + col]);
                asm volatile(
                    "mma.sync.aligned.m16n8k8.row.col.f32.tf32.tf32.f32 "
                    "{%0,%1,%2,%3}, {%4,%5,%6,%7}, {%8,%9}, {%0,%1,%2,%3};"
                    : "+f"(acc[nt][0]), "+f"(acc[nt][1]), "+f"(acc[nt][2]), "+f"(acc[nt][3])
                    : "r"(a0), "r"(a1), "r"(a2), "r"(a3), "r"(b0), "r"(b1));
            }
        }
    }

    int r_lo = row0 + warp * 16 + gid;
    int r_hi = r_lo + 8;
#pragma unroll
    for (int nt = 0; nt < 16; nt++) {
        int c = nt * 8 + 2 * tig;
        if (r_lo < N) {
            *reinterpret_cast<float2*>(g_xw + (size_t)r_lo * F + c) =
                make_float2(acc[nt][0], acc[nt][1]);
            *reinterpret_cast<__half2*>(g_xwh + (size_t)r_lo * F + c) =
                __float22half2_rn(make_float2(acc[nt][0], acc[nt][1]));
        }
        if (r_hi < N) {
            *reinterpret_cast<float2*>(g_xw + (size_t)r_hi * F + c) =
                make_float2(acc[nt][2], acc[nt][3]);
            *reinterpret_cast<__half2*>(g_xwh + (size_t)r_hi * F + c) =
                __float22half2_rn(make_float2(acc[nt][2], acc[nt][3]));
        }
    }
}

// ---------------------------------------------------------------------------
// 4) Fused aggregation + tanh + linear output. Warp per dst node.
//    fp16 gathers, 8-deep MLP; segment end read from g_cur (= off + cnt).
// ---------------------------------------------------------------------------
__global__ void k_agg_out(const float* __restrict__ wlin,
                          const float* __restrict__ blin,
                          float* __restrict__ out, int N) {
    int node = (blockIdx.x * blockDim.x + threadIdx.x) >> 5;
    int lane = threadIdx.x & 31;
    if (node >= N) return;

    float di = g_dinv[node];
    float4 v0 = reinterpret_cast<const float4*>(g_xw + (size_t)node * F)[lane];
    float sc = di * di;
    float ax = sc * v0.x, ay = sc * v0.y, az = sc * v0.z, aw = sc * v0.w;

    int e = g_off[node];
    int end = g_cur[node];          // off + cnt after placement

    for (; e + 8 <= end; e += 8) {
        int2 q[8];
        uint2 a[8];
#pragma unroll
        for (int i = 0; i < 8; i++) q[i] = __ldg(g_edge + e + i);
#pragma unroll
        for (int i = 0; i < 8; i++)
            a[i] = __ldg(reinterpret_cast<const uint2*>(g_xwh + (size_t)q[i].x * F) + lane);
#pragma unroll
        for (int i = 0; i < 8; i++) {
            float c = __int_as_float(q[i].y);
            float2 lo = __half22float2(*reinterpret_cast<__half2*>(&a[i].x));
            float2 hi = __half22float2(*reinterpret_cast<__half2*>(&a[i].y));
            ax += c * lo.x; ay += c * lo.y; az += c * hi.x; aw += c * hi.y;
        }
    }
    for (; e + 2 <= end; e += 2) {
        int2 q0 = __ldg(g_edge + e);
        int2 q1 = __ldg(g_edge + e + 1);
        uint2 a0 = __ldg(reinterpret_cast<const uint2*>(g_xwh + (size_t)q0.x * F) + lane);
        uint2 a1 = __ldg(reinterpret_cast<const uint2*>(g_xwh + (size_t)q1.x * F) + lane);
        float c0 = __int_as_float(q0.y), c1 = __int_as_float(q1.y);
        float2 lo0 = __half22float2(*reinterpret_cast<__half2*>(&a0.x));
        float2 hi0 = __half22float2(*reinterpret_cast<__half2*>(&a0.y));
        float2 lo1 = __half22float2(*reinterpret_cast<__half2*>(&a1.x));
        float2 hi1 = __half22float2(*reinterpret_cast<__half2*>(&a1.y));
        ax += c0 * lo0.x + c1 * lo1.x;
        ay += c0 * lo0.y + c1 * lo1.y;
        az += c0 * hi0.x + c1 * hi1.x;
        aw += c0 * hi0.y + c1 * hi1.y;
    }
    if (e < end) {
        int2 q = __ldg(g_edge + e);
        uint2 a = __ldg(reinterpret_cast<const uint2*>(g_xwh + (size_t)q.x * F) + lane);
        float c = __int_as_float(q.y);
        float2 lo = __half22float2(*reinterpret_cast<__half2*>(&a.x));
        float2 hi = __half22float2(*reinterpret_cast<__half2*>(&a.y));
        ax += c * lo.x; ay += c * lo.y; az += c * hi.x; aw += c * hi.y;
    }

    float4 wv = reinterpret_cast<const float4*>(wlin)[lane];
    float sum = tanhf(ax) * wv.x + tanhf(ay) * wv.y +
                tanhf(az) * wv.z + tanhf(aw) * wv.w;
#pragma unroll
    for (int o = 16; o; o >>= 1) sum += __shfl_xor_sync(0xffffffffu, sum, o);
    if (lane == 0) out[node] = sum + __ldg(blin);
}

// ---------------------------------------------------------------------------
extern "C" void kernel_launch(void* const* d_in, const int* in_sizes, int n_in,
                              void* d_out, int out_size) {
    const float* x    = (const float*)d_in[0];
    const int*   ei   = (const int*)d_in[1];
    const float* ew   = (const float*)d_in[2];
    const float* W0   = (const float*)d_in[3];
    const float* Wih  = (const float*)d_in[4];
    const float* Whh  = (const float*)d_in[5];
    const float* bih  = (const float*)d_in[6];
    const float* bhh  = (const float*)d_in[7];
    const float* wlin = (const float*)d_in[8];
    const float* blin = (const float*)d_in[9];
    float* out = (float*)d_out;

    int N = in_sizes[0] / F;
    int E = in_sizes[2];
    const int* src = ei;
    const int* dst = ei + E;
    int nb = (N + 255) / 256;                       // 196 for N=50000 (<=256)
    int gruBlocks = (F * F + 255) / 256;            // 64
    int histBlocks = (E + 511) / 512;               // 2 edges/thread
    int gemmBlocks = (N + 127) / 128;               // 16x128 tile (R11 config)
    int placeBlocks = (E + 511) / 512;

    k_gru_hist<<<gruBlocks + histBlocks, 256>>>(W0, Wih, Whh, bih, bhh,
                                                dst, ew, E, gruBlocks);
    k_scan<<<nb, 256>>>(N);
    k_place_gemm<<<gemmBlocks + placeBlocks, 256>>>(src, dst, ew, E, x, N, gemmBlocks);
    k_agg_out<<<(N + 7) / 8, 256>>>(wlin, blin, out, N);
}

// round 15
// speedup vs baseline: 1.0843x; 1.0346x over previous
#include <cuda_runtime.h>
#include <cuda_fp16.h>
#include <math.h>
#include <stdint.h>

#define F 128
#define MAXN 50048
#define MAXE 800064

// Scratch (__device__ globals; no allocation allowed).
// INVARIANT at kernel_launch entry (zero-init at load, restored every round):
//   g_cnt == 0, g_deg == 0, g_scanstate == 0.
__device__ __align__(16) float g_W[F * F];              // evolved weight
__device__ __align__(16) float g_xw[(size_t)MAXN * F];  // x @ W (fp32, self term)
__device__ __align__(16) __half g_xwh[(size_t)MAXN * F];// x @ W (fp16, gathers)
__device__ float g_dinv[MAXN];                          // rsqrt(deg)
__device__ float g_deg[MAXN];                           // weighted degree accum (zero-invariant)
__device__ int   g_cnt[MAXN];                           // per-dst edge count (zero-invariant)
__device__ int   g_off[MAXN];                           // exclusive scan
__device__ int   g_cur[MAXN];                           // placement cursors (end = off+cnt after place)
__device__ unsigned g_scanstate[256];                   // per-block aggregates (zero-invariant)
__device__ __align__(16) int2 g_edge[MAXE];             // dst-sorted (src, coef)

__device__ __forceinline__ uint32_t f2tf32(float f) {
    uint32_t u;
    asm("cvt.rna.tf32.f32 %0, %1;" : "=r"(u) : "f"(f));
    return u;
}

// ---------------------------------------------------------------------------
// 1) FUSED: GRU weight evolution (blocks [0,gruBlocks)) + edge histogram.
// ---------------------------------------------------------------------------
__global__ void k_gru_hist(const float* __restrict__ W0,
                           const float* __restrict__ Wih,
                           const float* __restrict__ Whh,
                           const float* __restrict__ bih,
                           const float* __restrict__ bhh,
                           const int* __restrict__ dst,
                           const float* __restrict__ ew, int E, int gruBlocks) {
    if ((int)blockIdx.x >= gruBlocks) {
        // ---------------- histogram: 2 edges/thread ----------------
        int t = (blockIdx.x - gruBlocks) * blockDim.x + threadIdx.x;
        int e0 = t * 2;
        if (e0 + 1 < E) {
            int2 dd = __ldg(reinterpret_cast<const int2*>(dst) + t);
            float2 ww = __ldg(reinterpret_cast<const float2*>(ew) + t);
            atomicAdd(&g_cnt[dd.x], 1);
            atomicAdd(&g_deg[dd.x], ww.x);
            atomicAdd(&g_cnt[dd.y], 1);
            atomicAdd(&g_deg[dd.y], ww.y);
        } else if (e0 < E) {
            int d = __ldg(dst + e0);
            atomicAdd(&g_cnt[d], 1);
            atomicAdd(&g_deg[d], __ldg(ew + e0));
        }
        return;
    }

    int t = blockIdx.x * blockDim.x + threadIdx.x;
    if (t >= F * F) return;
    int i = t >> 7;
    int j = t & 127;

    const float* w0r = W0 + i * F;
    const float* a_r = Wih + (size_t)j * F;
    const float* a_z = Wih + (size_t)(j + F) * F;
    const float* a_n = Wih + (size_t)(j + 2 * F) * F;
    const float* h_r = Whh + (size_t)j * F;
    const float* h_z = Whh + (size_t)(j + F) * F;
    const float* h_n = Whh + (size_t)(j + 2 * F) * F;

    float ir = 0.f, iz = 0.f, in_ = 0.f, hr = 0.f, hz = 0.f, hn = 0.f;
#pragma unroll 8
    for (int k = 0; k < F; k++) {
        float w0 = __ldg(w0r + k);
        ir += w0 * __ldg(a_r + k);
        iz += w0 * __ldg(a_z + k);
        in_ += w0 * __ldg(a_n + k);
        hr += w0 * __ldg(h_r + k);
        hz += w0 * __ldg(h_z + k);
        hn += w0 * __ldg(h_n + k);
    }
    ir += __ldg(bih + j);
    iz += __ldg(bih + j + F);
    in_ += __ldg(bih + j + 2 * F);
    hr += __ldg(bhh + j);
    hz += __ldg(bhh + j + F);
    hn += __ldg(bhh + j + 2 * F);

    float r = 1.f / (1.f + expf(-(ir + hr)));
    float z = 1.f / (1.f + expf(-(iz + hz)));
    float n = tanhf(in_ + r * hn);
    g_W[t] = (1.f - z) * n + z * __ldg(W0 + t);
}

// ---------------------------------------------------------------------------
// 2) Single-pass scan + dinv finalize + cursor init.
//    PARALLEL aggregate wait: every block publishes its aggregate; each
//    predecessor slot is polled by its own thread (nb <= 256), then a
//    block-wide reduction forms the prefix. No serial lookback chain.
//    Deadlock-free: blocks wait only on lower block ids (scheduled earlier;
//    all blocks fit in one wave at 196 CTAs).
// ---------------------------------------------------------------------------
__global__ void k_scan(int N) {
    __shared__ int sh[256];
    int tid = threadIdx.x;
    int gid = blockIdx.x * 256 + tid;

    int v = 0;
    if (gid < N) {
        float d = g_deg[gid];
        g_deg[gid] = 0.f;                       // restore invariant
        g_dinv[gid] = rsqrtf(d + 1.0f);         // +1 = self-loop weight; deg>=1
        v = g_cnt[gid];
        g_cnt[gid] = 0;                         // restore invariant
    }
    sh[tid] = v;
    __syncthreads();
#pragma unroll
    for (int o = 1; o < 256; o <<= 1) {
        int t = (tid >= o) ? sh[tid - o] : 0;
        __syncthreads();
        sh[tid] += t;
        __syncthreads();
    }
    int excl = sh[tid] - v;                     // exclusive within block
    int total = sh[255];

    // publish this block's aggregate
    if (tid == 0)
        atomicExch(&g_scanstate[blockIdx.x], (1u << 30) | (unsigned)total);

    // parallel wait: thread tid spins on predecessor block tid's aggregate
    int prev = 0;
    if (tid < (int)blockIdx.x) {
        unsigned s;
        do { s = atomicAdd(&g_scanstate[tid], 0u); } while (!(s >> 30));
        prev = (int)(s & 0x3FFFFFFFu);
    }
    __syncthreads();                            // sh free for reuse
    sh[tid] = prev;
    __syncthreads();
#pragma unroll
    for (int o = 128; o; o >>= 1) {
        if (tid < o) sh[tid] += sh[tid + o];
        __syncthreads();
    }
    int base = sh[0];

    if (gid < N) {
        int off = base + excl;
        g_off[gid] = off;
        g_cur[gid] = off;
    }
}

// ---------------------------------------------------------------------------
// 3) FUSED placement + tensor-core GEMM (16x128 warp tile).
//    First placement block also restores g_scanstate invariant.
// ---------------------------------------------------------------------------
__global__ void __launch_bounds__(256) k_place_gemm(
        const int* __restrict__ src, const int* __restrict__ dst,
        const float* __restrict__ ew, int E,
        const float* __restrict__ x, int N, int gemmBlocks) {

    if ((int)blockIdx.x >= gemmBlocks) {
        // ---------------- placement: 2 edges/thread ----------------
        if ((int)blockIdx.x == gemmBlocks)
            g_scanstate[threadIdx.x] = 0;       // restore invariant (scan done)
        int t = (blockIdx.x - gemmBlocks) * blockDim.x + threadIdx.x;
        int e0 = t * 2;
        if (e0 + 1 < E) {
            int2 ss = __ldg(reinterpret_cast<const int2*>(src) + t);
            int2 dd = __ldg(reinterpret_cast<const int2*>(dst) + t);
            float2 ww = __ldg(reinterpret_cast<const float2*>(ew) + t);
            float c0 = g_dinv[ss.x] * ww.x * g_dinv[dd.x];
            float c1 = g_dinv[ss.y] * ww.y * g_dinv[dd.y];
            int p0 = atomicAdd(&g_cur[dd.x], 1);
            g_edge[p0] = make_int2(ss.x, __float_as_int(c0));
            int p1 = atomicAdd(&g_cur[dd.y], 1);
            g_edge[p1] = make_int2(ss.y, __float_as_int(c1));
        } else if (e0 < E) {
            int s = __ldg(src + e0);
            int d = __ldg(dst + e0);
            float c = g_dinv[s] * __ldg(ew + e0) * g_dinv[d];
            int p = atomicAdd(&g_cur[d], 1);
            g_edge[p] = make_int2(s, __float_as_int(c));
        }
        return;
    }

    // ---------------- GEMM: g_xw = x @ g_W (tf32 mma, fp32 accum) ---------
    __shared__ float Xs[128 * 36];
    __shared__ float Ws[32 * 136];
    int tid = threadIdx.x;
    int warp = tid >> 5, lane = tid & 31;
    int row0 = blockIdx.x * 128;
    int gid = lane >> 2;
    int tig = lane & 3;

    float acc[16][4];
#pragma unroll
    for (int nt = 0; nt < 16; nt++)
#pragma unroll
        for (int c = 0; c < 4; c++) acc[nt][c] = 0.f;

    for (int kt = 0; kt < 4; kt++) {
        __syncthreads();
#pragma unroll
        for (int i = 0; i < 4; i++) {
            int e = tid + i * 256;
            int r = e >> 3, kg = e & 7;
            float4 v = make_float4(0.f, 0.f, 0.f, 0.f);
            if (row0 + r < N)
                v = __ldg(reinterpret_cast<const float4*>(x + (size_t)(row0 + r) * F + kt * 32) + kg);
            v.x = __uint_as_float(f2tf32(v.x));
            v.y = __uint_as_float(f2tf32(v.y));
            v.z = __uint_as_float(f2tf32(v.z));
            v.w = __uint_as_float(f2tf32(v.w));
            reinterpret_cast<float4*>(Xs)[r * 9 + kg] = v;
        }
#pragma unroll
        for (int i = 0; i < 4; i++) {
            int e = tid + i * 256;
            int r = e >> 5, cg = e & 31;
            float4 v = reinterpret_cast<const float4*>(g_W + (size_t)(kt * 32 + r) * F)[cg];
            v.x = __uint_as_float(f2tf32(v.x));
            v.y = __uint_as_float(f2tf32(v.y));
            v.z = __uint_as_float(f2tf32(v.z));
            v.w = __uint_as_float(f2tf32(v.w));
            reinterpret_cast<float4*>(Ws)[r * 34 + cg] = v;
        }
        __syncthreads();

#pragma unroll
        for (int ks = 0; ks < 4; ks++) {
            int k0 = ks * 8;
            int ar = warp * 16 + gid;
            uint32_t a0 = __float_as_uint(Xs[ar * 36 + k0 + tig]);
            uint32_t a1 = __float_as_uint(Xs[(ar + 8) * 36 + k0 + tig]);
            uint32_t a2 = __float_as_uint(Xs[ar * 36 + k0 + tig + 4]);
            uint32_t a3 = __float_as_uint(Xs[(ar + 8) * 36 + k0 + tig + 4]);
#pragma unroll
            for (int nt = 0; nt < 16; nt++) {
                int col = nt * 8 + gid;
                uint32_t b0 = __float_as_uint(Ws[(k0 + tig) * 136 + col]);
                uint32_t b1 = __float_as_uint(Ws[(k0 + tig + 4) * 136 + col]);
                asm volatile(
                    "mma.sync.aligned.m16n8k8.row.col.f32.tf32.tf32.f32 "
                    "{%0,%1,%2,%3}, {%4,%5,%6,%7}, {%8,%9}, {%0,%1,%2,%3};"
                    : "+f"(acc[nt][0]), "+f"(acc[nt][1]), "+f"(acc[nt][2]), "+f"(acc[nt][3])
                    : "r"(a0), "r"(a1), "r"(a2), "r"(a3), "r"(b0), "r"(b1));
            }
        }
    }

    int r_lo = row0 + warp * 16 + gid;
    int r_hi = r_lo + 8;
#pragma unroll
    for (int nt = 0; nt < 16; nt++) {
        int c = nt * 8 + 2 * tig;
        if (r_lo < N) {
            *reinterpret_cast<float2*>(g_xw + (size_t)r_lo * F + c) =
                make_float2(acc[nt][0], acc[nt][1]);
            *reinterpret_cast<__half2*>(g_xwh + (size_t)r_lo * F + c) =
                __float22half2_rn(make_float2(acc[nt][0], acc[nt][1]));
        }
        if (r_hi < N) {
            *reinterpret_cast<float2*>(g_xw + (size_t)r_hi * F + c) =
                make_float2(acc[nt][2], acc[nt][3]);
            *reinterpret_cast<__half2*>(g_xwh + (size_t)r_hi * F + c) =
                __float22half2_rn(make_float2(acc[nt][2], acc[nt][3]));
        }
    }
}

// ---------------------------------------------------------------------------
// 4) Fused aggregation + tanh + linear output. Warp per dst node.
//    fp16 gathers, 8-deep MLP; segment end read from g_cur (= off + cnt).
// ---------------------------------------------------------------------------
__global__ void k_agg_out(const float* __restrict__ wlin,
                          const float* __restrict__ blin,
                          float* __restrict__ out, int N) {
    int node = (blockIdx.x * blockDim.x + threadIdx.x) >> 5;
    int lane = threadIdx.x & 31;
    if (node >= N) return;

    float di = g_dinv[node];
    float4 v0 = reinterpret_cast<const float4*>(g_xw + (size_t)node * F)[lane];
    float sc = di * di;
    float ax = sc * v0.x, ay = sc * v0.y, az = sc * v0.z, aw = sc * v0.w;

    int e = g_off[node];
    int end = g_cur[node];          // off + cnt after placement

    for (; e + 8 <= end; e += 8) {
        int2 q[8];
        uint2 a[8];
#pragma unroll
        for (int i = 0; i < 8; i++) q[i] = __ldg(g_edge + e + i);
#pragma unroll
        for (int i = 0; i < 8; i++)
            a[i] = __ldg(reinterpret_cast<const uint2*>(g_xwh + (size_t)q[i].x * F) + lane);
#pragma unroll
        for (int i = 0; i < 8; i++) {
            float c = __int_as_float(q[i].y);
            float2 lo = __half22float2(*reinterpret_cast<__half2*>(&a[i].x));
            float2 hi = __half22float2(*reinterpret_cast<__half2*>(&a[i].y));
            ax += c * lo.x; ay += c * lo.y; az += c * hi.x; aw += c * hi.y;
        }
    }
    for (; e + 2 <= end; e += 2) {
        int2 q0 = __ldg(g_edge + e);
        int2 q1 = __ldg(g_edge + e + 1);
        uint2 a0 = __ldg(reinterpret_cast<const uint2*>(g_xwh + (size_t)q0.x * F) + lane);
        uint2 a1 = __ldg(reinterpret_cast<const uint2*>(g_xwh + (size_t)q1.x * F) + lane);
        float c0 = __int_as_float(q0.y), c1 = __int_as_float(q1.y);
        float2 lo0 = __half22float2(*reinterpret_cast<__half2*>(&a0.x));
        float2 hi0 = __half22float2(*reinterpret_cast<__half2*>(&a0.y));
        float2 lo1 = __half22float2(*reinterpret_cast<__half2*>(&a1.x));
        float2 hi1 = __half22float2(*reinterpret_cast<__half2*>(&a1.y));
        ax += c0 * lo0.x + c1 * lo1.x;
        ay += c0 * lo0.y + c1 * lo1.y;
        az += c0 * hi0.x + c1 * hi1.x;
        aw += c0 * hi0.y + c1 * hi1.y;
    }
    if (e < end) {
        int2 q = __ldg(g_edge + e);
        uint2 a = __ldg(reinterpret_cast<const uint2*>(g_xwh + (size_t)q.x * F) + lane);
        float c = __int_as_float(q.y);
        float2 lo = __half22float2(*reinterpret_cast<__half2*>(&a.x));
        float2 hi = __half22float2(*reinterpret_cast<__half2*>(&a.y));
        ax += c * lo.x; ay += c * lo.y; az += c * hi.x; aw += c * hi.y;
    }

    float4 wv = reinterpret_cast<const float4*>(wlin)[lane];
    float sum = tanhf(ax) * wv.x + tanhf(ay) * wv.y +
                tanhf(az) * wv.z + tanhf(aw) * wv.w;
#pragma unroll
    for (int o = 16; o; o >>= 1) sum += __shfl_xor_sync(0xffffffffu, sum, o);
    if (lane == 0) out[node] = sum + __ldg(blin);
}

// ---------------------------------------------------------------------------
extern "C" void kernel_launch(void* const* d_in, const int* in_sizes, int n_in,
                              void* d_out, int out_size) {
    const float* x    = (const float*)d_in[0];
    const int*   ei   = (const int*)d_in[1];
    const float* ew   = (const float*)d_in[2];
    const float* W0   = (const float*)d_in[3];
    const float* Wih  = (const float*)d_in[4];
    const float* Whh  = (const float*)d_in[5];
    const float* bih  = (const float*)d_in[6];
    const float* bhh  = (const float*)d_in[7];
    const float* wlin = (const float*)d_in[8];
    const float* blin = (const float*)d_in[9];
    float* out = (float*)d_out;

    int N = in_sizes[0] / F;
    int E = in_sizes[2];
    const int* src = ei;
    const int* dst = ei + E;
    int nb = (N + 255) / 256;                       // 196 for N=50000 (<=256)
    int gruBlocks = (F * F + 255) / 256;            // 64
    int histBlocks = (E + 511) / 512;               // 2 edges/thread
    int gemmBlocks = (N + 127) / 128;               // 16x128 tile
    int placeBlocks = (E + 511) / 512;

    k_gru_hist<<<gruBlocks + histBlocks, 256>>>(W0, Wih, Whh, bih, bhh,
                                                dst, ew, E, gruBlocks);
    k_scan<<<nb, 256>>>(N);
    k_place_gemm<<<gemmBlocks + placeBlocks, 256>>>(src, dst, ew, E, x, N, gemmBlocks);
    k_agg_out<<<(N + 7) / 8, 256>>>(wlin, blin, out, N);
}

// round 16
// speedup vs baseline: 2.0467x; 1.8876x over previous
#include <cuda_runtime.h>
#include <cuda_fp16.h>
#include <math.h>
#include <stdint.h>

#define F 128
#define MAXN 50048
#define MAXE 800064

// Scratch (__device__ globals; no allocation allowed).
// INVARIANT at kernel_launch entry (zero at load, restored every round):
//   g_pack == 0, g_scanstate == 0, g_histdone == 0, g_scandone == 0.
__device__ __align__(16) float g_W[F * F];               // evolved weight
__device__ __align__(16) __half g_xwh[(size_t)MAXN * F]; // x @ W (fp16)
__device__ float g_dinv[MAXN];                           // rsqrt(deg)
__device__ unsigned long long g_pack[MAXN];              // cnt<<40 | deg*2^24 (zero-invariant)
__device__ int   g_off[MAXN];                            // exclusive scan
__device__ int   g_cur[MAXN];                            // cursors (end = off+cnt after place)
__device__ unsigned g_scanstate[256];                    // per-block aggregates (zero-invariant)
__device__ unsigned g_histdone;                          // hist completion counter (zero-invariant)
__device__ unsigned g_scandone;                          // scan completion counter (zero-invariant)
__device__ __align__(16) int2 g_edge[MAXE];              // dst-sorted (src, coef)

__device__ __forceinline__ uint32_t f2tf32(float f) {
    uint32_t u;
    asm("cvt.rna.tf32.f32 %0, %1;" : "=r"(u) : "f"(f));
    return u;
}

// ---------------------------------------------------------------------------
// 1) MEGA-FUSED pre-pass: GRU evolve | edge histogram | scan.
//    blocks [0,GRU_B): GRU (float4 loads, 4x MLP vs scalar).
//    blocks [GRU_B, GRU_B+histBlocks): histogram slice (1 packed u64
//      atomic/edge), then signal g_histdone.
//    blocks [GRU_B, GRU_B+scanBlocks): additionally spin until all hist
//      slices land, then run the block scan + parallel aggregate wait.
//    Deadlock-safe: only scanBlocks(196) blocks spin; they can't fill the
//    (>=592-slot) resident wave, so every hist block gets scheduled.
// ---------------------------------------------------------------------------
#define GRU_B 64

__global__ void __launch_bounds__(256) k_pre(
        const float* __restrict__ W0,
        const float* __restrict__ Wih,
        const float* __restrict__ Whh,
        const float* __restrict__ bih,
        const float* __restrict__ bhh,
        const int* __restrict__ dst,
        const float* __restrict__ ew, int E,
        int histBlocks, int scanBlocks, int N) {

    int b = blockIdx.x;
    int tid = threadIdx.x;

    if (b < GRU_B) {
        // -------------------- GRU weight evolution --------------------
        int t = b * 256 + tid;
        int i = t >> 7;
        int j = t & 127;
        const float4* w0r = reinterpret_cast<const float4*>(W0 + (size_t)i * F);
        const float4* a_r = reinterpret_cast<const float4*>(Wih + (size_t)j * F);
        const float4* a_z = reinterpret_cast<const float4*>(Wih + (size_t)(j + F) * F);
        const float4* a_n = reinterpret_cast<const float4*>(Wih + (size_t)(j + 2 * F) * F);
        const float4* h_r = reinterpret_cast<const float4*>(Whh + (size_t)j * F);
        const float4* h_z = reinterpret_cast<const float4*>(Whh + (size_t)(j + F) * F);
        const float4* h_n = reinterpret_cast<const float4*>(Whh + (size_t)(j + 2 * F) * F);

        float ir = 0.f, iz = 0.f, in_ = 0.f, hr = 0.f, hz = 0.f, hn = 0.f;
#pragma unroll 4
        for (int k = 0; k < 32; k++) {
            float4 w0 = __ldg(w0r + k);
            float4 v;
            v = __ldg(a_r + k); ir += w0.x * v.x + w0.y * v.y + w0.z * v.z + w0.w * v.w;
            v = __ldg(a_z + k); iz += w0.x * v.x + w0.y * v.y + w0.z * v.z + w0.w * v.w;
            v = __ldg(a_n + k); in_ += w0.x * v.x + w0.y * v.y + w0.z * v.z + w0.w * v.w;
            v = __ldg(h_r + k); hr += w0.x * v.x + w0.y * v.y + w0.z * v.z + w0.w * v.w;
            v = __ldg(h_z + k); hz += w0.x * v.x + w0.y * v.y + w0.z * v.z + w0.w * v.w;
            v = __ldg(h_n + k); hn += w0.x * v.x + w0.y * v.y + w0.z * v.z + w0.w * v.w;
        }
        ir += __ldg(bih + j);
        iz += __ldg(bih + j + F);
        in_ += __ldg(bih + j + 2 * F);
        hr += __ldg(bhh + j);
        hz += __ldg(bhh + j + F);
        hn += __ldg(bhh + j + 2 * F);

        float r = 1.f / (1.f + expf(-(ir + hr)));
        float z = 1.f / (1.f + expf(-(iz + hz)));
        float n = tanhf(in_ + r * hn);
        g_W[t] = (1.f - z) * n + z * __ldg(W0 + t);
        return;
    }

    int hb = b - GRU_B;               // hist block id (0..histBlocks-1)
    {
        // -------------------- histogram slice: 2 edges/thread ----------
        int t = hb * 256 + tid;
        int e0 = t * 2;
        if (e0 + 1 < E) {
            int2 dd = __ldg(reinterpret_cast<const int2*>(dst) + t);
            float2 ww = __ldg(reinterpret_cast<const float2*>(ew) + t);
            unsigned long long i0 = (1ULL << 40) |
                (unsigned long long)__float2uint_rn(ww.x * 16777216.f);
            unsigned long long i1 = (1ULL << 40) |
                (unsigned long long)__float2uint_rn(ww.y * 16777216.f);
            atomicAdd(&g_pack[dd.x], i0);
            atomicAdd(&g_pack[dd.y], i1);
        } else if (e0 < E) {
            int d = __ldg(dst + e0);
            unsigned long long i0 = (1ULL << 40) |
                (unsigned long long)__float2uint_rn(__ldg(ew + e0) * 16777216.f);
            atomicAdd(&g_pack[d], i0);
        }
        __syncthreads();
        __threadfence();
        if (tid == 0) atomicAdd(&g_histdone, 1u);
    }
    if (hb >= scanBlocks) return;

    // -------------------- scan (after all hist slices land) ------------
    if (tid == 0) {
        while (atomicAdd(&g_histdone, 0u) < (unsigned)histBlocks) {}
        __threadfence();
    }
    __syncthreads();

    __shared__ int sh[256];
    int gid = hb * 256 + tid;
    int v = 0;
    if (gid < N) {
        unsigned long long p = g_pack[gid];
        g_pack[gid] = 0ULL;                        // restore invariant
        v = (int)(p >> 40);
        float d = (float)(p & ((1ULL << 40) - 1)) * (1.f / 16777216.f);
        g_dinv[gid] = rsqrtf(d + 1.0f);            // +1 = self-loop; deg >= 1
    }
    sh[tid] = v;
    __syncthreads();
#pragma unroll
    for (int o = 1; o < 256; o <<= 1) {
        int t = (tid >= o) ? sh[tid - o] : 0;
        __syncthreads();
        sh[tid] += t;
        __syncthreads();
    }
    int excl = sh[tid] - v;
    int total = sh[255];

    if (tid == 0)
        atomicExch(&g_scanstate[hb], (1u << 30) | (unsigned)total);

    int prev = 0;
    if (tid < hb) {
        unsigned s;
        do { s = atomicAdd(&g_scanstate[tid], 0u); } while (!(s >> 30));
        prev = (int)(s & 0x3FFFFFFFu);
    }
    __syncthreads();
    sh[tid] = prev;
    __syncthreads();
#pragma unroll
    for (int o = 128; o; o >>= 1) {
        if (tid < o) sh[tid] += sh[tid + o];
        __syncthreads();
    }
    int base = sh[0];

    if (gid < N) {
        int off = base + excl;
        g_off[gid] = off;
        g_cur[gid] = off;
    }

    // restore counters once the LAST scan block finishes
    __syncthreads();
    if (tid == 0) {
        unsigned done = atomicAdd(&g_scandone, 1u) + 1u;
        if (done == (unsigned)scanBlocks) {
            g_histdone = 0u;
            g_scandone = 0u;
        }
    }
}

// ---------------------------------------------------------------------------
// 2) FUSED placement + tensor-core GEMM (16x128 warp tile, fp16-only epilogue).
//    First placement block restores g_scanstate invariant.
// ---------------------------------------------------------------------------
__global__ void __launch_bounds__(256) k_place_gemm(
        const int* __restrict__ src, const int* __restrict__ dst,
        const float* __restrict__ ew, int E,
        const float* __restrict__ x, int N, int gemmBlocks) {

    if ((int)blockIdx.x >= gemmBlocks) {
        // ---------------- placement: 2 edges/thread ----------------
        if ((int)blockIdx.x == gemmBlocks)
            g_scanstate[threadIdx.x] = 0;       // restore invariant (scan done)
        int t = (blockIdx.x - gemmBlocks) * blockDim.x + threadIdx.x;
        int e0 = t * 2;
        if (e0 + 1 < E) {
            int2 ss = __ldg(reinterpret_cast<const int2*>(src) + t);
            int2 dd = __ldg(reinterpret_cast<const int2*>(dst) + t);
            float2 ww = __ldg(reinterpret_cast<const float2*>(ew) + t);
            float c0 = g_dinv[ss.x] * ww.x * g_dinv[dd.x];
            float c1 = g_dinv[ss.y] * ww.y * g_dinv[dd.y];
            int p0 = atomicAdd(&g_cur[dd.x], 1);
            g_edge[p0] = make_int2(ss.x, __float_as_int(c0));
            int p1 = atomicAdd(&g_cur[dd.y], 1);
            g_edge[p1] = make_int2(ss.y, __float_as_int(c1));
        } else if (e0 < E) {
            int s = __ldg(src + e0);
            int d = __ldg(dst + e0);
            float c = g_dinv[s] * __ldg(ew + e0) * g_dinv[d];
            int p = atomicAdd(&g_cur[d], 1);
            g_edge[p] = make_int2(s, __float_as_int(c));
        }
        return;
    }

    // ---------------- GEMM: xwh = x @ g_W (tf32 mma, fp32 accum) ----------
    __shared__ float Xs[128 * 36];
    __shared__ float Ws[32 * 136];
    int tid = threadIdx.x;
    int warp = tid >> 5, lane = tid & 31;
    int row0 = blockIdx.x * 128;
    int gid = lane >> 2;
    int tig = lane & 3;

    float acc[16][4];
#pragma unroll
    for (int nt = 0; nt < 16; nt++)
#pragma unroll
        for (int c = 0; c < 4; c++) acc[nt][c] = 0.f;

    for (int kt = 0; kt < 4; kt++) {
        __syncthreads();
#pragma unroll
        for (int i = 0; i < 4; i++) {
            int e = tid + i * 256;
            int r = e >> 3, kg = e & 7;
            float4 v = make_float4(0.f, 0.f, 0.f, 0.f);
            if (row0 + r < N)
                v = __ldg(reinterpret_cast<const float4*>(x + (size_t)(row0 + r) * F + kt * 32) + kg);
            v.x = __uint_as_float(f2tf32(v.x));
            v.y = __uint_as_float(f2tf32(v.y));
            v.z = __uint_as_float(f2tf32(v.z));
            v.w = __uint_as_float(f2tf32(v.w));
            reinterpret_cast<float4*>(Xs)[r * 9 + kg] = v;
        }
#pragma unroll
        for (int i = 0; i < 4; i++) {
            int e = tid + i * 256;
            int r = e >> 5, cg = e & 31;
            float4 v = reinterpret_cast<const float4*>(g_W + (size_t)(kt * 32 + r) * F)[cg];
            v.x = __uint_as_float(f2tf32(v.x));
            v.y = __uint_as_float(f2tf32(v.y));
            v.z = __uint_as_float(f2tf32(v.z));
            v.w = __uint_as_float(f2tf32(v.w));
            reinterpret_cast<float4*>(Ws)[r * 34 + cg] = v;
        }
        __syncthreads();

#pragma unroll
        for (int ks = 0; ks < 4; ks++) {
            int k0 = ks * 8;
            int ar = warp * 16 + gid;
            uint32_t a0 = __float_as_uint(Xs[ar * 36 + k0 + tig]);
            uint32_t a1 = __float_as_uint(Xs[(ar + 8) * 36 + k0 + tig]);
            uint32_t a2 = __float_as_uint(Xs[ar * 36 + k0 + tig + 4]);
            uint32_t a3 = __float_as_uint(Xs[(ar + 8) * 36 + k0 + tig + 4]);
#pragma unroll
            for (int nt = 0; nt < 16; nt++) {
                int col = nt * 8 + gid;
                uint32_t b0 = __float_as_uint(Ws[(k0 + tig) * 136 + col]);
                uint32_t b1 = __float_as_uint(Ws[(k0 + tig + 4) * 136 + col]);
                asm volatile(
                    "mma.sync.aligned.m16n8k8.row.col.f32.tf32.tf32.f32 "
                    "{%0,%1,%2,%3}, {%4,%5,%6,%7}, {%8,%9}, {%0,%1,%2,%3};"
                    : "+f"(acc[nt][0]), "+f"(acc[nt][1]), "+f"(acc[nt][2]), "+f"(acc[nt][3])
                    : "r"(a0), "r"(a1), "r"(a2), "r"(a3), "r"(b0), "r"(b1));
            }
        }
    }

    int r_lo = row0 + warp * 16 + gid;
    int r_hi = r_lo + 8;
#pragma unroll
    for (int nt = 0; nt < 16; nt++) {
        int c = nt * 8 + 2 * tig;
        if (r_lo < N)
            *reinterpret_cast<__half2*>(g_xwh + (size_t)r_lo * F + c) =
                __float22half2_rn(make_float2(acc[nt][0], acc[nt][1]));
        if (r_hi < N)
            *reinterpret_cast<__half2*>(g_xwh + (size_t)r_hi * F + c) =
                __float22half2_rn(make_float2(acc[nt][2], acc[nt][3]));
    }
}

// ---------------------------------------------------------------------------
// 3) Fused aggregation + tanh + linear output. Warp per dst node.
//    All gathers fp16 (self term included); 8-deep MLP.
// ---------------------------------------------------------------------------
__global__ void k_agg_out(const float* __restrict__ wlin,
                          const float* __restrict__ blin,
                          float* __restrict__ out, int N) {
    int node = (blockIdx.x * blockDim.x + threadIdx.x) >> 5;
    int lane = threadIdx.x & 31;
    if (node >= N) return;

    float di = g_dinv[node];
    float sc = di * di;
    uint2 sv = __ldg(reinterpret_cast<const uint2*>(g_xwh + (size_t)node * F) + lane);
    float2 slo = __half22float2(*reinterpret_cast<__half2*>(&sv.x));
    float2 shi = __half22float2(*reinterpret_cast<__half2*>(&sv.y));
    float ax = sc * slo.x, ay = sc * slo.y, az = sc * shi.x, aw = sc * shi.y;

    int e = g_off[node];
    int end = g_cur[node];          // off + cnt after placement

    for (; e + 8 <= end; e += 8) {
        int2 q[8];
        uint2 a[8];
#pragma unroll
        for (int i = 0; i < 8; i++) q[i] = __ldg(g_edge + e + i);
#pragma unroll
        for (int i = 0; i < 8; i++)
            a[i] = __ldg(reinterpret_cast<const uint2*>(g_xwh + (size_t)q[i].x * F) + lane);
#pragma unroll
        for (int i = 0; i < 8; i++) {
            float c = __int_as_float(q[i].y);
            float2 lo = __half22float2(*reinterpret_cast<__half2*>(&a[i].x));
            float2 hi = __half22float2(*reinterpret_cast<__half2*>(&a[i].y));
            ax += c * lo.x; ay += c * lo.y; az += c * hi.x; aw += c * hi.y;
        }
    }
    for (; e + 2 <= end; e += 2) {
        int2 q0 = __ldg(g_edge + e);
        int2 q1 = __ldg(g_edge + e + 1);
        uint2 a0 = __ldg(reinterpret_cast<const uint2*>(g_xwh + (size_t)q0.x * F) + lane);
        uint2 a1 = __ldg(reinterpret_cast<const uint2*>(g_xwh + (size_t)q1.x * F) + lane);
        float c0 = __int_as_float(q0.y), c1 = __int_as_float(q1.y);
        float2 lo0 = __half22float2(*reinterpret_cast<__half2*>(&a0.x));
        float2 hi0 = __half22float2(*reinterpret_cast<__half2*>(&a0.y));
        float2 lo1 = __half22float2(*reinterpret_cast<__half2*>(&a1.x));
        float2 hi1 = __half22float2(*reinterpret_cast<__half2*>(&a1.y));
        ax += c0 * lo0.x + c1 * lo1.x;
        ay += c0 * lo0.y + c1 * lo1.y;
        az += c0 * hi0.x + c1 * hi1.x;
        aw += c0 * hi0.y + c1 * hi1.y;
    }
    if (e < end) {
        int2 q = __ldg(g_edge + e);
        uint2 a = __ldg(reinterpret_cast<const uint2*>(g_xwh + (size_t)q.x * F) + lane);
        float c = __int_as_float(q.y);
        float2 lo = __half22float2(*reinterpret_cast<__half2*>(&a.x));
        float2 hi = __half22float2(*reinterpret_cast<__half2*>(&a.y));
        ax += c * lo.x; ay += c * lo.y; az += c * hi.x; aw += c * hi.y;
    }

    float4 wv = reinterpret_cast<const float4*>(wlin)[lane];
    float sum = tanhf(ax) * wv.x + tanhf(ay) * wv.y +
                tanhf(az) * wv.z + tanhf(aw) * wv.w;
#pragma unroll
    for (int o = 16; o; o >>= 1) sum += __shfl_xor_sync(0xffffffffu, sum, o);
    if (lane == 0) out[node] = sum + __ldg(blin);
}

// ---------------------------------------------------------------------------
extern "C" void kernel_launch(void* const* d_in, const int* in_sizes, int n_in,
                              void* d_out, int out_size) {
    const float* x    = (const float*)d_in[0];
    const int*   ei   = (const int*)d_in[1];
    const float* ew   = (const float*)d_in[2];
    const float* W0   = (const float*)d_in[3];
    const float* Wih  = (const float*)d_in[4];
    const float* Whh  = (const float*)d_in[5];
    const float* bih  = (const float*)d_in[6];
    const float* bhh  = (const float*)d_in[7];
    const float* wlin = (const float*)d_in[8];
    const float* blin = (const float*)d_in[9];
    float* out = (float*)d_out;

    int N = in_sizes[0] / F;
    int E = in_sizes[2];
    const int* src = ei;
    const int* dst = ei + E;
    int scanBlocks = (N + 255) / 256;               // 196 for N=50000 (<=256)
    int histBlocks = (E + 511) / 512;               // 2 edges/thread (>= scanBlocks)
    int gemmBlocks = (N + 127) / 128;               // 16x128 tile
    int placeBlocks = (E + 511) / 512;

    k_pre<<<GRU_B + histBlocks, 256>>>(W0, Wih, Whh, bih, bhh,
                                       dst, ew, E, histBlocks, scanBlocks, N);
    k_place_gemm<<<gemmBlocks + placeBlocks, 256>>>(src, dst, ew, E, x, N, gemmBlocks);
    k_agg_out<<<(N + 7) / 8, 256>>>(wlin, blin, out, N);
}